// round 15
// baseline (speedup 1.0000x reference)
#include <cuda_runtime.h>
#include <cuda_bf16.h>
#include <cuda_fp16.h>

#define NN 100000
#define NE 1600000
#define NP 200000

// ================= scratch (device globals) =================
__device__ int   g_is64;
__device__ __align__(16) float g_deg[NN];   // 1/deg
__device__ __align__(16) float g_dis[NN];   // 1/sqrt(deg)
__device__ int   g_cnt[NN];
__device__ int   g_off[NN + 1];
__device__ int   g_cur[NN];
__device__ int   g_src[NE];
__device__ int   g_dst[NE];
__device__ int   g_csrc[NE];
__device__ __align__(16) __half g_msg[NN * 128];   // fp16 messages Hs
__device__ __align__(16) float g_bufB[NN * 128];
__device__ __align__(16) float g_bufC[NN * 128];
// W^T splits for ALL layers: bf16 [n][k], k-stride 128; banks at 0 / 16384 / 32768 elems
__device__ __align__(16) __nv_bfloat16 g_Wh[3 * 128 * 128];
__device__ __align__(16) __nv_bfloat16 g_Wl[3 * 128 * 128];

// ================= helpers =================
__device__ __forceinline__ unsigned smem_u32(const void* p) {
    unsigned a;
    asm("{ .reg .u64 t; cvta.to.shared.u64 t, %1; cvt.u32.u64 %0, t; }"
        : "=r"(a) : "l"(p));
    return a;
}

__device__ __forceinline__ void ldsm4(unsigned* r, unsigned addr) {
    asm volatile("ldmatrix.sync.aligned.m8n8.x4.shared.b16 {%0,%1,%2,%3}, [%4];"
                 : "=r"(r[0]), "=r"(r[1]), "=r"(r[2]), "=r"(r[3]) : "r"(addr));
}

__device__ __forceinline__ void mma16816(float* d, const unsigned* a, const unsigned* b) {
    asm volatile("mma.sync.aligned.m16n8k16.row.col.f32.bf16.bf16.f32 "
                 "{%0,%1,%2,%3}, {%4,%5,%6,%7}, {%8,%9}, {%0,%1,%2,%3};"
                 : "+f"(d[0]), "+f"(d[1]), "+f"(d[2]), "+f"(d[3])
                 : "r"(a[0]), "r"(a[1]), "r"(a[2]), "r"(a[3]), "r"(b[0]), "r"(b[1]));
}

__device__ __forceinline__ unsigned pack2(float a, float b) {
    __nv_bfloat162 t(__float2bfloat16_rn(a), __float2bfloat16_rn(b));
    return *reinterpret_cast<unsigned*>(&t);
}
__device__ __forceinline__ unsigned pack_hi(float a, float b, float& ra, float& rb) {
    __nv_bfloat16 ha = __float2bfloat16_rn(a), hb = __float2bfloat16_rn(b);
    ra = a - __bfloat162float(ha);
    rb = b - __bfloat162float(hb);
    __nv_bfloat162 t(ha, hb);
    return *reinterpret_cast<unsigned*>(&t);
}

__device__ __forceinline__ int load_idx(const void* p, int i) {
    if (g_is64) return (int)((const long long*)p)[i];
    return ((const int*)p)[i];
}

// ================= prep (fused) =================
// zero histogram + index-dtype detection in one launch
__global__ void k_zd(const void* __restrict__ ei) {
    int i = blockIdx.x * 256 + threadIdx.x;
    if (i < NN) g_cnt[i] = 0;
    if (i == 0) {
        const unsigned* p = (const unsigned*)ei;
        unsigned acc = 0;
        #pragma unroll
        for (int k = 0; k < 16; k++) acc |= p[2 * k + 1];
        g_is64 = (acc == 0u) ? 1 : 0;
    }
}

__global__ void k_prep(const void* __restrict__ ei) {
    int e = blockIdx.x * 256 + threadIdx.x;
    if (e >= NE) return;
    int s = load_idx(ei, e);
    int d = load_idx(ei, NE + e);
    g_src[e] = s;
    g_dst[e] = d;
    atomicAdd(&g_cnt[d], 1);
}

// single-block exclusive scan of g_cnt -> g_off/g_cur, fused deg/dis finalize
__global__ __launch_bounds__(1024) void k_scanfin() {
    __shared__ int chunk[1024];
    const int C = (NN + 1023) / 1024;   // 98
    int t = threadIdx.x;
    int base = t * C;
    int s = 0;
    for (int i = 0; i < C; i++) {
        int idx = base + i;
        if (idx < NN) s += g_cnt[idx];
    }
    chunk[t] = s;
    __syncthreads();
    for (int o = 1; o < 1024; o <<= 1) {
        int v = (t >= o) ? chunk[t - o] : 0;
        __syncthreads();
        chunk[t] += v;
        __syncthreads();
    }
    int pre = (t == 0) ? 0 : chunk[t - 1];
    for (int i = 0; i < C; i++) {
        int idx = base + i;
        if (idx < NN) {
            g_off[idx] = pre;
            g_cur[idx] = pre;
            int c = g_cnt[idx];
            float deg = (float)c + 1.f;
            g_deg[idx] = 1.f / deg;
            g_dis[idx] = rsqrtf(deg);
            pre += c;
        }
    }
    if (t == 1023) g_off[NN] = pre;
}

__global__ void k_place() {
    int e = blockIdx.x * 256 + threadIdx.x;
    if (e >= NE) return;
    int d = g_dst[e];
    int p = atomicAdd(&g_cur[d], 1);
    g_csrc[p] = g_src[e];
}

// ================= W prep: ALL layers, transpose + bf16 split ==========
// layer banks: L1 @0 (128x128), L2 @16384 (128x128), L3 @32768 (64x128)
__global__ void k_convAll(const float* __restrict__ W1, const float* __restrict__ W2,
                          const float* __restrict__ W3) {
    int t = blockIdx.x * 256 + threadIdx.x;
    const float* W;
    int cout, bank;
    if (t < 4096)       { W = W1; cout = 128; bank = 0; }
    else if (t < 8192)  { W = W2; cout = 128; bank = 16384; t -= 4096; }
    else if (t < 10240) { W = W3; cout = 64;  bank = 32768; t -= 8192; }
    else return;
    int n  = t >> 5;
    int k0 = (t & 31) * 4;
    float w0 = W[(k0 + 0) * cout + n];
    float w1 = W[(k0 + 1) * cout + n];
    float w2 = W[(k0 + 2) * cout + n];
    float w3 = W[(k0 + 3) * cout + n];
    float r0, r1, r2, r3;
    unsigned h01 = pack_hi(w0, w1, r0, r1);
    unsigned h23 = pack_hi(w2, w3, r2, r3);
    unsigned l01 = pack2(r0, r1);
    unsigned l23 = pack2(r2, r3);
    unsigned off = (unsigned)(bank + n * 128 + k0) * 2;
    *(uint2*)((char*)g_Wh + off) = make_uint2(h01, h23);
    *(uint2*)((char*)g_Wl + off) = make_uint2(l01, l23);
}

// ================= mma.sync GEMM =================
// h = act(X) @ W ; msg = fp16(h*dis) ; AGG = h/deg + b
// CTA: 256 thr (8 warps), tile 64 rows x COUT. Warp grid 4x2, warp tile 16 x COUT/2.
// 3-term bf16 split: XhWh + XhWl + XlWh, fp32 accum.
#define SA 136   // smem k-stride in elems (272B: ldmatrix conflict-free)

template <int COUT, bool RELU>
__global__ __launch_bounds__(256, 2) void k_mma_gemm(
    const float* __restrict__ X, const float* __restrict__ bias,
    const __nv_bfloat16* __restrict__ Wh, const __nv_bfloat16* __restrict__ Wl,
    __half* __restrict__ Hs, float* __restrict__ AGG)
{
    extern __shared__ char sm[];
    constexpr int ASZ = 64 * SA * 2;         // bytes per A split matrix (17408)
    constexpr int BSZ = COUT * SA * 2;       // bytes per B split matrix
    char* sAh = sm;
    char* sAl = sm + ASZ;
    char* sBh = sm + 2 * ASZ;
    char* sBl = sm + 2 * ASZ + BSZ;
    const unsigned uAh = smem_u32(sAh), uAl = smem_u32(sAl);
    const unsigned uBh = smem_u32(sBh), uBl = smem_u32(sBl);

    const int tid = threadIdx.x;
    const int wid = tid >> 5;
    const int lane = tid & 31;
    const int base = blockIdx.x * 64;
    constexpr int NT = COUT / 16;            // n8-tiles per warp (8 or 4)

    // ---- A: load fp32 X tile, (ReLU), split bf16 hi/lo ----
    {
        const float4* X4 = (const float4*)X;
        #pragma unroll
        for (int i = tid; i < 64 * 32; i += 256) {
            int r = i >> 5;
            int k0 = (i & 31) * 4;
            int gr = base + r;
            float4 v = make_float4(0.f, 0.f, 0.f, 0.f);
            if (gr < NN) v = X4[gr * 32 + (k0 >> 2)];
            if (RELU) {
                v.x = fmaxf(v.x, 0.f); v.y = fmaxf(v.y, 0.f);
                v.z = fmaxf(v.z, 0.f); v.w = fmaxf(v.w, 0.f);
            }
            float rx, ry, rz, rw;
            unsigned h01 = pack_hi(v.x, v.y, rx, ry);
            unsigned h23 = pack_hi(v.z, v.w, rz, rw);
            unsigned off = (unsigned)(r * SA + k0) * 2;
            *(uint2*)(sAh + off) = make_uint2(h01, h23);
            *(uint2*)(sAl + off) = make_uint2(pack2(rx, ry), pack2(rz, rw));
        }
    }
    // ---- B: copy W^T splits (bf16 [n][128]) into padded smem ----
    {
        #pragma unroll
        for (int i = tid; i < COUT * 32; i += 256) {
            int n = i >> 5;
            int k0 = (i & 31) * 4;
            unsigned soff = (unsigned)(n * SA + k0) * 2;
            unsigned goff = (unsigned)(n * 128 + k0) * 2;
            *(uint2*)(sBh + soff) = *(const uint2*)((const char*)Wh + goff);
            *(uint2*)(sBl + soff) = *(const uint2*)((const char*)Wl + goff);
        }
    }
    __syncthreads();

    const int wr = wid & 3;
    const int wc = wid >> 2;
    const int m0 = wr * 16;
    const int n0 = wc * (COUT / 2);

    float acc[NT][4];
    #pragma unroll
    for (int j = 0; j < NT; j++)
        #pragma unroll
        for (int q = 0; q < 4; q++) acc[j][q] = 0.f;

    // intra-warp ldmatrix lane offsets
    const unsigned aoff = (unsigned)((m0 + (lane & 15)) * SA + (lane >> 4) * 8) * 2;
    const int bmat = lane >> 3;              // 0..3
    const int brow = lane & 7;
    const unsigned boff_row = (unsigned)((n0 + (bmat >> 1) * 8 + brow) * SA + (bmat & 1) * 8) * 2;

    #pragma unroll
    for (int ks = 0; ks < 8; ks++) {
        const unsigned k2 = (unsigned)(ks * 16) * 2;
        unsigned ah[4], al[4];
        ldsm4(ah, uAh + aoff + k2);
        ldsm4(al, uAl + aoff + k2);

        unsigned bh[NT][2], bl[NT][2];
        #pragma unroll
        for (int jj = 0; jj < NT / 2; jj++) {
            unsigned bo = boff_row + (unsigned)(jj * 16 * SA) * 2 + k2;
            unsigned t4[4];
            ldsm4(t4, uBh + bo);
            bh[jj * 2][0] = t4[0]; bh[jj * 2][1] = t4[1];
            bh[jj * 2 + 1][0] = t4[2]; bh[jj * 2 + 1][1] = t4[3];
            ldsm4(t4, uBl + bo);
            bl[jj * 2][0] = t4[0]; bl[jj * 2][1] = t4[1];
            bl[jj * 2 + 1][0] = t4[2]; bl[jj * 2 + 1][1] = t4[3];
        }
        #pragma unroll
        for (int j = 0; j < NT; j++) {
            mma16816(acc[j], ah, bh[j]);
            mma16816(acc[j], ah, bl[j]);
            mma16816(acc[j], al, bh[j]);
        }
    }

    // ---- epilogue: msg = fp16(h*dis) ; AGG = h/deg + b ----
    {
        const int r1 = m0 + (lane >> 2);
        const int r2 = r1 + 8;
        const int gr1 = base + r1;
        const int gr2 = base + r2;
        float ds1 = 0.f, di1 = 0.f, ds2 = 0.f, di2 = 0.f;
        if (gr1 < NN) { ds1 = g_dis[gr1]; di1 = g_deg[gr1]; }
        if (gr2 < NN) { ds2 = g_dis[gr2]; di2 = g_deg[gr2]; }
        #pragma unroll
        for (int j = 0; j < NT; j++) {
            const int col = n0 + j * 8 + (lane & 3) * 2;
            const float2 bv = *(const float2*)(bias + col);
            if (gr1 < NN) {
                *(__half2*)(Hs + gr1 * COUT + col) =
                    __floats2half2_rn(acc[j][0] * ds1, acc[j][1] * ds1);
                float2 ag = make_float2(acc[j][0] * di1 + bv.x, acc[j][1] * di1 + bv.y);
                *(float2*)(AGG + gr1 * COUT + col) = ag;
            }
            if (gr2 < NN) {
                *(__half2*)(Hs + gr2 * COUT + col) =
                    __floats2half2_rn(acc[j][2] * ds2, acc[j][3] * ds2);
                float2 ag = make_float2(acc[j][2] * di2 + bv.x, acc[j][3] * di2 + bv.y);
                *(float2*)(AGG + gr2 * COUT + col) = ag;
            }
        }
    }
}

// ======= gather aggregation (fp16 msgs): AGG[d] += dis[d]*sum msg[src] =====
template <int COUT>
__global__ __launch_bounds__(256) void k_agg(const __half* __restrict__ Hs,
                                             float* __restrict__ AGG)
{
    constexpr int LPN = COUT / 8;        // uint4 lanes per node (16 or 8)
    constexpr int NPB = 256 / LPN;       // nodes per block (16 or 32)
    int n = blockIdx.x * NPB + threadIdx.x / LPN;
    int lane = threadIdx.x % LPN;
    if (n >= NN) return;

    int beg = g_off[n];
    int end = g_off[n + 1];
    float2 a0 = make_float2(0.f, 0.f), a1 = a0, a2 = a0, a3 = a0;
    const uint4* H4 = (const uint4*)Hs;

    #define ADDV(v) do { \
        float2 f0 = __half22float2(*(const __half2*)&(v).x); \
        float2 f1 = __half22float2(*(const __half2*)&(v).y); \
        float2 f2 = __half22float2(*(const __half2*)&(v).z); \
        float2 f3 = __half22float2(*(const __half2*)&(v).w); \
        a0.x += f0.x; a0.y += f0.y; a1.x += f1.x; a1.y += f1.y; \
        a2.x += f2.x; a2.y += f2.y; a3.x += f3.x; a3.y += f3.y; \
    } while (0)

    int e = beg;
    for (; e + 3 < end; e += 4) {
        int s0 = g_csrc[e];
        int s1 = g_csrc[e + 1];
        int s2 = g_csrc[e + 2];
        int s3 = g_csrc[e + 3];
        uint4 v0 = H4[s0 * LPN + lane];
        uint4 v1 = H4[s1 * LPN + lane];
        uint4 v2 = H4[s2 * LPN + lane];
        uint4 v3 = H4[s3 * LPN + lane];
        ADDV(v0); ADDV(v1); ADDV(v2); ADDV(v3);
    }
    for (; e < end; e++) {
        uint4 v = H4[g_csrc[e] * LPN + lane];
        ADDV(v);
    }
    #undef ADDV

    float ds = g_dis[n];
    float4* row = (float4*)(AGG + n * COUT + lane * 8);
    float4 o0 = row[0];
    float4 o1 = row[1];
    o0.x += ds * a0.x; o0.y += ds * a0.y; o0.z += ds * a1.x; o0.w += ds * a1.y;
    o1.x += ds * a2.x; o1.y += ds * a2.y; o1.z += ds * a3.x; o1.w += ds * a3.y;
    row[0] = o0;
    row[1] = o1;
}

// ================= pair dot decode =================
__global__ __launch_bounds__(256) void k_pairs(
    const float* __restrict__ H,
    const void* __restrict__ ni, const void* __restrict__ nj,
    float* __restrict__ out)
{
    int t = blockIdx.x * 256 + threadIdx.x;
    int p = t >> 5;
    int lane = t & 31;
    if (p >= NP) return;
    int i = load_idx(ni, p);
    int j = load_idx(nj, p);
    float2 a = ((const float2*)H)[i * 32 + lane];
    float2 b = ((const float2*)H)[j * 32 + lane];
    float s = a.x * b.x + a.y * b.y;
    #pragma unroll
    for (int o = 16; o; o >>= 1) s += __shfl_xor_sync(0xFFFFFFFFu, s, o);
    if (lane == 0) out[p] = s;
}

// ================= launch =================
extern "C" void kernel_launch(void* const* d_in, const int* in_sizes, int n_in,
                              void* d_out, int out_size)
{
    const float* x  = (const float*)d_in[0];
    const void*  ei = d_in[1];
    const void*  ni = d_in[2];
    const void*  nj = d_in[3];
    const float* W1 = (const float*)d_in[4];
    const float* b1 = (const float*)d_in[5];
    const float* W2 = (const float*)d_in[6];
    const float* b2 = (const float*)d_in[7];
    const float* W3 = (const float*)d_in[8];
    const float* b3 = (const float*)d_in[9];
    float* out = (float*)d_out;

    __half* msg;
    float *bufB, *bufC;
    __nv_bfloat16 *wh, *wl;
    cudaGetSymbolAddress((void**)&msg,  g_msg);
    cudaGetSymbolAddress((void**)&bufB, g_bufB);
    cudaGetSymbolAddress((void**)&bufC, g_bufC);
    cudaGetSymbolAddress((void**)&wh,   g_Wh);
    cudaGetSymbolAddress((void**)&wl,   g_Wl);

    const int smem128 = 2 * (64 * SA * 2) + 2 * (128 * SA * 2);  // 104448
    const int smem64  = 2 * (64 * SA * 2) + 2 * (64 * SA * 2);   //  69632
    cudaFuncSetAttribute(k_mma_gemm<128, false>, cudaFuncAttributeMaxDynamicSharedMemorySize, smem128);
    cudaFuncSetAttribute(k_mma_gemm<128, true>,  cudaFuncAttributeMaxDynamicSharedMemorySize, smem128);
    cudaFuncSetAttribute(k_mma_gemm<64,  true>,  cudaFuncAttributeMaxDynamicSharedMemorySize, smem64);

    // prep: dtype detect + degree/CSR + all W conversions up front
    k_zd<<<(NN + 255) / 256, 256>>>(ei);
    k_prep<<<(NE + 255) / 256, 256>>>(ei);
    k_scanfin<<<1, 1024>>>();
    k_place<<<(NE + 255) / 256, 256>>>();
    k_convAll<<<40, 256>>>(W1, W2, W3);

    const int gt = (NN + 63) / 64;   // 1563 tiles

    // layer 1
    k_mma_gemm<128, false><<<gt, 256, smem128>>>(x, b1, wh, wl, msg, bufB);
    k_agg<128><<<(NN + 15) / 16, 256>>>(msg, bufB);
    // layer 2
    k_mma_gemm<128, true><<<gt, 256, smem128>>>(bufB, b2, wh + 16384, wl + 16384, msg, bufC);
    k_agg<128><<<(NN + 15) / 16, 256>>>(msg, bufC);
    // layer 3 (COUT=64)
    k_mma_gemm<64, true><<<gt, 256, smem64>>>(bufC, b3, wh + 32768, wl + 32768, msg, bufB);
    k_agg<64><<<(NN + 31) / 32, 256>>>(msg, bufB);

    // link decode
    k_pairs<<<(NP * 32) / 256, 256>>>(bufB, ni, nj, out);
}